// round 1
// baseline (speedup 1.0000x reference)
#include <cuda_runtime.h>
#include <math.h>

#define NN 50000
#define NE 800000
#define NET 850000
#define F 128
#define NG 256
#define NCLS 10

// ---------------- device scratch (static, no allocation) ----------------
__device__ __align__(16) float g_h0[NN * F];
__device__ __align__(16) float g_h1[NN * F];
__device__ __align__(16) float g_hp[NN * F];
__device__ __align__(16) float g_als[NN * 4];
__device__ __align__(16) float g_ald[NN * 4];
__device__ int   g_deg[NN];
__device__ int   g_off[NN + 1];
__device__ int   g_cur[NN];
__device__ int   g_csrc[NET];
__device__ float g_stats[2 * F];
__device__ __align__(16) float g_Wf[F * F];
__device__ __align__(16) float g_bf[F];
__device__ __align__(16) float g_pool[NG * F];
__device__ __align__(16) float g_gbuf[NG * F];

// selectors: 0=external ptr, 1=h0, 2=h1, 3=hp, 4=pool, 5=gbuf
__device__ __forceinline__ const float* sel_ptr(int sel, const float* ext) {
    switch (sel) {
        case 1: return g_h0;
        case 2: return g_h1;
        case 3: return g_hp;
        case 4: return g_pool;
        case 5: return g_gbuf;
        default: return ext;
    }
}
__device__ __forceinline__ float* sel_ptr_w(int sel) {
    switch (sel) {
        case 1: return g_h0;
        case 2: return g_h1;
        case 3: return g_hp;
        case 4: return g_pool;
        default: return g_gbuf;
    }
}

// ---------------- CSR construction ----------------
__global__ void k_initdeg() {
    int i = blockIdx.x * blockDim.x + threadIdx.x;
    if (i < NN) g_deg[i] = 1;  // self loop
}

__global__ void k_count(const int* __restrict__ ei) {
    int e = blockIdx.x * blockDim.x + threadIdx.x;
    if (e < NE) atomicAdd(&g_deg[ei[NE + e]], 1);
}

__global__ void k_scan() {
    // exclusive scan of g_deg -> g_off, 1 block of 1024 threads
    __shared__ int warpsum[32];
    __shared__ int carry_sh;
    int tid = threadIdx.x;
    int lane = tid & 31, w = tid >> 5;
    if (tid == 0) carry_sh = 0;
    __syncthreads();
    for (int base = 0; base < NN; base += 1024) {
        int i = base + tid;
        int v = (i < NN) ? g_deg[i] : 0;
        int x = v;
#pragma unroll
        for (int o = 1; o < 32; o <<= 1) {
            int t = __shfl_up_sync(0xffffffffu, x, o);
            if (lane >= o) x += t;
        }
        if (lane == 31) warpsum[w] = x;
        __syncthreads();
        if (w == 0) {
            int s = warpsum[lane];
#pragma unroll
            for (int o = 1; o < 32; o <<= 1) {
                int t = __shfl_up_sync(0xffffffffu, s, o);
                if (lane >= o) s += t;
            }
            warpsum[lane] = s;
        }
        __syncthreads();
        int prefix = carry_sh + ((w > 0) ? warpsum[w - 1] : 0);
        if (i < NN) g_off[i] = prefix + x - v;
        __syncthreads();
        if (tid == 0) carry_sh += warpsum[31];
        __syncthreads();
    }
    if (tid == 0) g_off[NN] = carry_sh;
}

__global__ void k_copycur() {
    int i = blockIdx.x * blockDim.x + threadIdx.x;
    if (i < NN) g_cur[i] = g_off[i];
}

__global__ void k_fill(const int* __restrict__ ei) {
    int t = blockIdx.x * blockDim.x + threadIdx.x;
    if (t < NE) {
        int d = ei[NE + t];
        int p = atomicAdd(&g_cur[d], 1);
        g_csrc[p] = ei[t];
    } else if (t < NE + NN) {
        int i = t - NE;
        int p = atomicAdd(&g_cur[i], 1);
        g_csrc[p] = i;  // self loop
    }
}

// ---------------- BN statistics + fold ----------------
__global__ void k_zerostats() {
    int t = threadIdx.x;
    if (t < 2 * F) g_stats[t] = 0.f;
}

__global__ void k_colstats(const float* __restrict__ ext, int sel, int M) {
    const float* X = sel_ptr(sel, ext);
    int c = threadIdx.x;  // 128 threads
    int r0 = blockIdx.x * 64;
    int nr = M - r0;
    if (nr > 64) nr = 64;
    float s = 0.f, q = 0.f;
    for (int j = 0; j < nr; j++) {
        float v = X[(size_t)(r0 + j) * F + c];
        s += v;
        q += v * v;
    }
    atomicAdd(&g_stats[c], s);
    atomicAdd(&g_stats[F + c], q);
}

// fold BN(gamma,beta with stats) into W' = diag(scale)W, b' = shift@W (+extra)
__global__ void k_fold(const float* __restrict__ W, const float* __restrict__ gamma,
                       const float* __restrict__ beta, const float* __restrict__ extrab,
                       float invM) {
    __shared__ float sc[F], shf[F];
    int tid = threadIdx.x;  // 128
    float mean = g_stats[tid] * invM;
    float var = g_stats[F + tid] * invM - mean * mean;
    float rs = rsqrtf(var + 1e-5f);
    float s = rs * gamma[tid];
    sc[tid] = s;
    shf[tid] = beta[tid] - mean * s;
    __syncthreads();
    float bj = extrab ? extrab[tid] : 0.f;
    for (int c = 0; c < F; c++) {
        float w = W[(size_t)c * F + tid];
        g_Wf[(size_t)c * F + tid] = sc[c] * w;
        bj += shf[c] * w;
    }
    g_bf[tid] = bj;
}

// ---------------- SGEMM: C[M,128] = A[M,128] @ g_Wf + g_bf, optional relu ----------------
__global__ __launch_bounds__(256) void k_gemm(const float* __restrict__ ext_in, int sel_in,
                                              int sel_out, int M, int relu) {
    const float* A = sel_ptr(sel_in, ext_in);
    float* C = sel_ptr_w(sel_out);
    __shared__ float As[128][17];
    __shared__ float Bs[16][128];
    __shared__ float bsh[128];
    int tid = threadIdx.x;
    if (tid < 128) bsh[tid] = g_bf[tid];
    int row0 = blockIdx.x * 128;
    int tx = tid & 15, ty = tid >> 4;
    float acc[8][8];
#pragma unroll
    for (int i = 0; i < 8; i++)
#pragma unroll
        for (int j = 0; j < 8; j++) acc[i][j] = 0.f;

    for (int k0 = 0; k0 < 128; k0 += 16) {
#pragma unroll
        for (int t = tid; t < 512; t += 256) {
            int r = t >> 2, c4 = t & 3;
            int gr = row0 + r;
            float4 v = make_float4(0.f, 0.f, 0.f, 0.f);
            if (gr < M) v = *(const float4*)(A + (size_t)gr * F + k0 + c4 * 4);
            As[r][c4 * 4 + 0] = v.x;
            As[r][c4 * 4 + 1] = v.y;
            As[r][c4 * 4 + 2] = v.z;
            As[r][c4 * 4 + 3] = v.w;
        }
#pragma unroll
        for (int t = tid; t < 512; t += 256) {
            int r = t >> 5, c4 = t & 31;
            *(float4*)(&Bs[r][c4 * 4]) = *(const float4*)(g_Wf + (size_t)(k0 + r) * F + c4 * 4);
        }
        __syncthreads();
#pragma unroll
        for (int k = 0; k < 16; k++) {
            float4 b0 = *(const float4*)(&Bs[k][tx * 8]);
            float4 b1 = *(const float4*)(&Bs[k][tx * 8 + 4]);
#pragma unroll
            for (int i = 0; i < 8; i++) {
                float a = As[ty * 8 + i][k];
                acc[i][0] += a * b0.x;
                acc[i][1] += a * b0.y;
                acc[i][2] += a * b0.z;
                acc[i][3] += a * b0.w;
                acc[i][4] += a * b1.x;
                acc[i][5] += a * b1.y;
                acc[i][6] += a * b1.z;
                acc[i][7] += a * b1.w;
            }
        }
        __syncthreads();
    }
#pragma unroll
    for (int i = 0; i < 8; i++) {
        int gr = row0 + ty * 8 + i;
        if (gr < M) {
            float4 o0, o1;
            o0.x = acc[i][0] + bsh[tx * 8 + 0];
            o0.y = acc[i][1] + bsh[tx * 8 + 1];
            o0.z = acc[i][2] + bsh[tx * 8 + 2];
            o0.w = acc[i][3] + bsh[tx * 8 + 3];
            o1.x = acc[i][4] + bsh[tx * 8 + 4];
            o1.y = acc[i][5] + bsh[tx * 8 + 5];
            o1.z = acc[i][6] + bsh[tx * 8 + 6];
            o1.w = acc[i][7] + bsh[tx * 8 + 7];
            if (relu) {
                o0.x = fmaxf(o0.x, 0.f); o0.y = fmaxf(o0.y, 0.f);
                o0.z = fmaxf(o0.z, 0.f); o0.w = fmaxf(o0.w, 0.f);
                o1.x = fmaxf(o1.x, 0.f); o1.y = fmaxf(o1.y, 0.f);
                o1.z = fmaxf(o1.z, 0.f); o1.w = fmaxf(o1.w, 0.f);
            }
            *(float4*)(C + (size_t)gr * F + tx * 8) = o0;
            *(float4*)(C + (size_t)gr * F + tx * 8 + 4) = o1;
        }
    }
}

// ---------------- attention alpha logits: al_s/al_d per node,head ----------------
__global__ void k_alpha(const float* __restrict__ asrc, const float* __restrict__ adst) {
    int i = blockIdx.x;
    int tid = threadIdx.x;  // 128
    float v = g_hp[(size_t)i * F + tid];
    float ps = v * asrc[tid];
    float pd = v * adst[tid];
#pragma unroll
    for (int o = 16; o; o >>= 1) {
        ps += __shfl_xor_sync(0xffffffffu, ps, o);
        pd += __shfl_xor_sync(0xffffffffu, pd, o);
    }
    int lane = tid & 31, w = tid >> 5;
    if (lane == 0) {
        g_als[i * 4 + w] = ps;
        g_ald[i * 4 + w] = pd;
    }
}

// ---------------- aggregation: warp per dst node ----------------
__global__ __launch_bounds__(256) void k_agg(const float* __restrict__ gbias, int sel_out) {
    float* out = sel_ptr_w(sel_out);
    int gw = (blockIdx.x * blockDim.x + threadIdx.x) >> 5;
    int lane = threadIdx.x & 31;
    if (gw >= NN) return;
    int s0 = g_off[gw], s1 = g_off[gw + 1];
    const float4* als4 = (const float4*)g_als;
    float4 aldv = ((const float4*)g_ald)[gw];

    // pass 1: per-head max of leaky_relu(als[src]+ald[dst]) (edge-parallel)
    float4 mx = make_float4(-3.0e38f, -3.0e38f, -3.0e38f, -3.0e38f);
    for (int e = s0 + lane; e < s1; e += 32) {
        int s = g_csrc[e];
        float4 a = als4[s];
        float lx = a.x + aldv.x; lx = lx > 0.f ? lx : 0.2f * lx;
        float ly = a.y + aldv.y; ly = ly > 0.f ? ly : 0.2f * ly;
        float lz = a.z + aldv.z; lz = lz > 0.f ? lz : 0.2f * lz;
        float lw = a.w + aldv.w; lw = lw > 0.f ? lw : 0.2f * lw;
        mx.x = fmaxf(mx.x, lx);
        mx.y = fmaxf(mx.y, ly);
        mx.z = fmaxf(mx.z, lz);
        mx.w = fmaxf(mx.w, lw);
    }
#pragma unroll
    for (int o = 16; o; o >>= 1) {
        mx.x = fmaxf(mx.x, __shfl_xor_sync(0xffffffffu, mx.x, o));
        mx.y = fmaxf(mx.y, __shfl_xor_sync(0xffffffffu, mx.y, o));
        mx.z = fmaxf(mx.z, __shfl_xor_sync(0xffffffffu, mx.z, o));
        mx.w = fmaxf(mx.w, __shfl_xor_sync(0xffffffffu, mx.w, o));
    }
    int h = lane >> 3;  // this lane's 4 columns all belong to head h
    float mh = (h == 0) ? mx.x : (h == 1) ? mx.y : (h == 2) ? mx.z : mx.w;
    float aldh = (h == 0) ? aldv.x : (h == 1) ? aldv.y : (h == 2) ? aldv.z : aldv.w;

    // pass 2: accumulate sum(exp) and weighted features (lanes cover full 128 cols)
    float a0 = 0.f, a1 = 0.f, a2 = 0.f, a3 = 0.f, ss = 0.f;
    const float4* hp4 = (const float4*)g_hp;
    for (int e = s0; e < s1; ++e) {
        int s = g_csrc[e];
        float l = g_als[s * 4 + h] + aldh;
        l = l > 0.f ? l : 0.2f * l;
        float wgt = __expf(l - mh);
        ss += wgt;
        float4 v = hp4[(size_t)s * 32 + lane];
        a0 += wgt * v.x;
        a1 += wgt * v.y;
        a2 += wgt * v.z;
        a3 += wgt * v.w;
    }
    float inv = 1.0f / (ss + 1e-16f);
    float4 gb = ((const float4*)gbias)[lane];
    float4 o;
    o.x = fmaxf(a0 * inv + gb.x, 0.f);
    o.y = fmaxf(a1 * inv + gb.y, 0.f);
    o.z = fmaxf(a2 * inv + gb.z, 0.f);
    o.w = fmaxf(a3 * inv + gb.w, 0.f);
    ((float4*)out)[(size_t)gw * 32 + lane] = o;
}

// ---------------- pooling (batch sorted) ----------------
__global__ void k_zeropool() {
    int i = blockIdx.x * blockDim.x + threadIdx.x;
    if (i < NG * F) g_pool[i] = 0.f;
}

__global__ void k_pool(const int* __restrict__ batch, int sel_in) {
    const float* X = sel_ptr(sel_in, nullptr);
    __shared__ int bsh[64];
    int r0 = blockIdx.x * 64;
    int tid = threadIdx.x;  // 128
    int nr = NN - r0;
    if (nr > 64) nr = 64;
    if (tid < nr) bsh[tid] = batch[r0 + tid];
    __syncthreads();
    float acc = 0.f;
    int cur = bsh[0];
    for (int j = 0; j < nr; j++) {
        int b = bsh[j];
        if (b != cur) {
            atomicAdd(&g_pool[(size_t)cur * F + tid], acc);
            acc = 0.f;
            cur = b;
        }
        acc += X[(size_t)(r0 + j) * F + tid];
    }
    atomicAdd(&g_pool[(size_t)cur * F + tid], acc);
}

// ---------------- final head: BN + cls GEMM + log_softmax ----------------
__global__ void k_head(const float* __restrict__ bnh_g, const float* __restrict__ bnh_b,
                       const float* __restrict__ cls_w, const float* __restrict__ cls_b,
                       float* __restrict__ out) {
    __shared__ float sc[F], shf[F];
    int r = blockIdx.x;       // 256 rows
    int lane = threadIdx.x;   // 32 threads
    const float invM = 1.0f / (float)NG;
    for (int c = lane; c < F; c += 32) {
        float mean = g_stats[c] * invM;
        float var = g_stats[F + c] * invM - mean * mean;
        float rs = rsqrtf(var + 1e-5f);
        float s = rs * bnh_g[c];
        sc[c] = s;
        shf[c] = bnh_b[c] - mean * s;
    }
    __syncwarp();
    float logit = 0.f;
    if (lane < NCLS) {
        logit = cls_b[lane];
        for (int c = 0; c < F; c++)
            logit += (g_gbuf[(size_t)r * F + c] * sc[c] + shf[c]) * cls_w[c * NCLS + lane];
    }
    float v = (lane < NCLS) ? logit : -3.0e38f;
    float m = v;
#pragma unroll
    for (int o = 16; o; o >>= 1) m = fmaxf(m, __shfl_xor_sync(0xffffffffu, m, o));
    float e = (lane < NCLS) ? __expf(v - m) : 0.f;
    float s = e;
#pragma unroll
    for (int o = 16; o; o >>= 1) s += __shfl_xor_sync(0xffffffffu, s, o);
    if (lane < NCLS) out[r * NCLS + lane] = v - m - logf(s);
}

// ---------------- host ----------------
extern "C" void kernel_launch(void* const* d_in, const int* in_sizes, int n_in,
                              void* d_out, int out_size) {
    const float* x       = (const float*)d_in[0];
    const int*   ei      = (const int*)d_in[1];
    const int*   batch   = (const int*)d_in[2];
    const float* w_feat  = (const float*)d_in[3];
    const float* bnf_g   = (const float*)d_in[4];
    const float* bnf_b   = (const float*)d_in[5];
    const float* bnc_g   = (const float*)d_in[6];
    const float* bnc_b   = (const float*)d_in[7];
    const float* gat_w   = (const float*)d_in[8];
    const float* gat_as  = (const float*)d_in[9];
    const float* gat_ad  = (const float*)d_in[10];
    const float* gat_b   = (const float*)d_in[11];
    const float* bnfc_g  = (const float*)d_in[12];
    const float* bnfc_b  = (const float*)d_in[13];
    const float* lin_w   = (const float*)d_in[14];
    const float* lin_b   = (const float*)d_in[15];
    const float* bnh_g   = (const float*)d_in[16];
    const float* bnh_b   = (const float*)d_in[17];
    const float* cls_w   = (const float*)d_in[18];
    const float* cls_b   = (const float*)d_in[19];
    float* out = (float*)d_out;

    // ---- CSR build (dst-indexed, with self loops) ----
    k_initdeg<<<(NN + 255) / 256, 256>>>();
    k_count<<<(NE + 255) / 256, 256>>>(ei);
    k_scan<<<1, 1024>>>();
    k_copycur<<<(NN + 255) / 256, 256>>>();
    k_fill<<<(NE + NN + 255) / 256, 256>>>(ei);

    // ---- feature layer: h0 = relu(BN(x) @ w_feat) ----
    k_zerostats<<<1, 256>>>();
    k_colstats<<<(NN + 63) / 64, 128>>>(x, 0, NN);
    k_fold<<<1, 128>>>(w_feat, bnf_g, bnf_b, nullptr, 1.0f / (float)NN);
    k_gemm<<<(NN + 127) / 128, 256>>>(x, 0, 1, NN, 1);

    // ---- 3 GAT convs ----
    int sel_in = 1, sel_out = 2;
    for (int i = 0; i < 3; i++) {
        k_zerostats<<<1, 256>>>();
        k_colstats<<<(NN + 63) / 64, 128>>>(nullptr, sel_in, NN);
        k_fold<<<1, 128>>>(gat_w + (size_t)i * F * F, bnc_g + i * F, bnc_b + i * F,
                           nullptr, 1.0f / (float)NN);
        k_gemm<<<(NN + 127) / 128, 256>>>(nullptr, sel_in, 3, NN, 0);  // hp = BN(h) @ W
        k_alpha<<<NN, 128>>>(gat_as + i * F, gat_ad + i * F);
        k_agg<<<(NN + 7) / 8, 256>>>(gat_b + i * F, sel_out);
        int t = sel_in; sel_in = sel_out; sel_out = t;
    }
    // after loop, final conv output is in sel_in (== 2, g_h1)

    // ---- pooling ----
    k_zeropool<<<(NG * F + 255) / 256, 256>>>();
    k_pool<<<(NN + 63) / 64, 128>>>(batch, sel_in);

    // ---- lin layer: gbuf = relu(BN(pool) @ lin_w + lin_b) ----
    k_zerostats<<<1, 256>>>();
    k_colstats<<<(NG + 63) / 64, 128>>>(nullptr, 4, NG);
    k_fold<<<1, 128>>>(lin_w, bnfc_g, bnfc_b, lin_b, 1.0f / (float)NG);
    k_gemm<<<(NG + 127) / 128, 256>>>(nullptr, 4, 5, NG, 1);

    // ---- head: BN(gbuf) @ cls + log_softmax ----
    k_zerostats<<<1, 256>>>();
    k_colstats<<<(NG + 63) / 64, 128>>>(nullptr, 5, NG);
    k_head<<<NG, 32>>>(bnh_g, bnh_b, cls_w, cls_b, out);
}

// round 2
// speedup vs baseline: 1.5191x; 1.5191x over previous
#include <cuda_runtime.h>
#include <math.h>

#define NN 50000
#define NE 800000
#define NET 850000
#define F 128
#define NG 256
#define NCLS 10

// ---------------- device scratch (static, no allocation) ----------------
__device__ __align__(16) float g_h0[NN * F];
__device__ __align__(16) float g_h1[NN * F];
__device__ __align__(16) float g_hp[NN * F];
__device__ __align__(16) float g_als[NN * 4];
__device__ __align__(16) float g_ald[NN * 4];
__device__ int   g_deg[NN];
__device__ int   g_off[NN + 1];
__device__ int   g_cur[NN];
__device__ int   g_bsum[128];
__device__ int   g_csrc[NET];
__device__ float g_stats[2 * F];
__device__ __align__(16) unsigned g_Wfrag[F * F];   // fragment-ready tf32 W'
__device__ __align__(16) float g_bf[F];
__device__ __align__(16) float g_pool[NG * F];
__device__ __align__(16) float g_gbuf[NG * F];

// selectors: 0=external ptr, 1=h0, 2=h1, 3=hp, 4=pool, 5=gbuf
__device__ __forceinline__ const float* sel_ptr(int sel, const float* ext) {
    switch (sel) {
        case 1: return g_h0;
        case 2: return g_h1;
        case 3: return g_hp;
        case 4: return g_pool;
        case 5: return g_gbuf;
        default: return ext;
    }
}
__device__ __forceinline__ float* sel_ptr_w(int sel) {
    switch (sel) {
        case 1: return g_h0;
        case 2: return g_h1;
        case 3: return g_hp;
        case 4: return g_pool;
        default: return g_gbuf;
    }
}

__device__ __forceinline__ unsigned f2tf(float x) {
    unsigned u;
    asm("cvt.rna.tf32.f32 %0, %1;" : "=r"(u) : "f"(x));
    return u;
}

__device__ __forceinline__ void mma_tf32(float* c, const unsigned* a, unsigned b0, unsigned b1) {
    asm volatile(
        "mma.sync.aligned.m16n8k8.row.col.f32.tf32.tf32.f32 "
        "{%0,%1,%2,%3},{%4,%5,%6,%7},{%8,%9},{%0,%1,%2,%3};"
        : "+f"(c[0]), "+f"(c[1]), "+f"(c[2]), "+f"(c[3])
        : "r"(a[0]), "r"(a[1]), "r"(a[2]), "r"(a[3]), "r"(b0), "r"(b1));
}

// ---------------- zero / init everything ----------------
__global__ void k_zeroall() {
    int i = blockIdx.x * blockDim.x + threadIdx.x;
    if (i < NN) g_deg[i] = 1;                 // self loop
    if (i < 2 * F) g_stats[i] = 0.f;
    if (i < NG * F) g_pool[i] = 0.f;
}

// ---------------- CSR construction ----------------
__global__ void k_count(const int* __restrict__ ei) {
    int e = blockIdx.x * blockDim.x + threadIdx.x;
    if (e < NE) atomicAdd(&g_deg[ei[NE + e]], 1);
}

#define SCAN_B 512
#define SCAN_NB ((NN + SCAN_B - 1) / SCAN_B)   // 98

__global__ void k_scanA() {
    __shared__ int wsum[16];
    int t = threadIdx.x, b = blockIdx.x;
    int i = b * SCAN_B + t;
    int v = (i < NN) ? g_deg[i] : 0;
    int lane = t & 31, w = t >> 5;
    int x = v;
#pragma unroll
    for (int o = 1; o < 32; o <<= 1) {
        int tv = __shfl_up_sync(0xffffffffu, x, o);
        if (lane >= o) x += tv;
    }
    if (lane == 31) wsum[w] = x;
    __syncthreads();
    if (w == 0) {
        int s = (lane < 16) ? wsum[lane] : 0;
#pragma unroll
        for (int o = 1; o < 16; o <<= 1) {
            int tv = __shfl_up_sync(0xffffffffu, s, o);
            if (lane >= o) s += tv;
        }
        if (lane < 16) wsum[lane] = s;
    }
    __syncthreads();
    int incl = x + ((w > 0) ? wsum[w - 1] : 0);
    if (i < NN) g_off[i] = incl - v;   // block-local exclusive
    if (t == SCAN_B - 1) g_bsum[b] = incl;
}

__global__ void k_scanB() {
    __shared__ int sh[128];
    int t = threadIdx.x;  // 128
    int v = (t < SCAN_NB) ? g_bsum[t] : 0;
    sh[t] = v;
    __syncthreads();
#pragma unroll
    for (int o = 1; o < 128; o <<= 1) {
        int p = (t >= o) ? sh[t - o] : 0;
        __syncthreads();
        sh[t] += p;
        __syncthreads();
    }
    if (t < SCAN_NB) g_bsum[t] = sh[t] - v;  // exclusive
    if (t == 127) g_off[NN] = sh[127];
}

__global__ void k_scanC() {
    int i = blockIdx.x * blockDim.x + threadIdx.x;
    if (i < NN) {
        int val = g_off[i] + g_bsum[i >> 9];
        g_off[i] = val;
        g_cur[i] = val;
    }
}

__global__ void k_fill(const int* __restrict__ ei) {
    int t = blockIdx.x * blockDim.x + threadIdx.x;
    if (t < NE) {
        int d = ei[NE + t];
        int p = atomicAdd(&g_cur[d], 1);
        g_csrc[p] = ei[t];
    } else if (t < NE + NN) {
        int i = t - NE;
        int p = atomicAdd(&g_cur[i], 1);
        g_csrc[p] = i;  // self loop
    }
}

// ---------------- BN statistics ----------------
__global__ void k_colstats(const float* __restrict__ ext, int sel, int M) {
    const float* X = sel_ptr(sel, ext);
    int c = threadIdx.x;  // 128 threads
    int r0 = blockIdx.x * 64;
    int nr = M - r0;
    if (nr > 64) nr = 64;
    float s = 0.f, q = 0.f;
    for (int j = 0; j < nr; j++) {
        float v = X[(size_t)(r0 + j) * F + c];
        s += v;
        q += v * v;
    }
    atomicAdd(&g_stats[c], s);
    atomicAdd(&g_stats[F + c], q);
}

// fold BN into W' = diag(scale)W, b' = shift@W (+extra); emit fragment-packed tf32 W'
// also zeroes g_stats for the next colstats pass
__global__ void k_fold(const float* __restrict__ W, const float* __restrict__ gamma,
                       const float* __restrict__ beta, const float* __restrict__ extrab,
                       float invM) {
    extern __shared__ float Wsh[];  // 128*128
    __shared__ float sc[F], shf[F];
    int tid = threadIdx.x;  // 128
    float mean = g_stats[tid] * invM;
    float var = g_stats[F + tid] * invM - mean * mean;
    float s = rsqrtf(var + 1e-5f) * gamma[tid];
    sc[tid] = s;
    shf[tid] = beta[tid] - mean * s;
    g_stats[tid] = 0.f;
    g_stats[F + tid] = 0.f;
    __syncthreads();
    float bj = extrab ? extrab[tid] : 0.f;
    for (int c = 0; c < F; c++) {
        float w = W[(size_t)c * F + tid];
        Wsh[c * F + tid] = sc[c] * w;
        bj += shf[c] * w;
    }
    g_bf[tid] = bj;
    __syncthreads();
    // fragment pack: idx = ((ks*16 + nt)*32 + lane)*2 + r
    for (int idx = tid; idx < F * F; idx += 128) {
        int r = idx & 1;
        int lane = (idx >> 1) & 31;
        int nt = (idx >> 6) & 15;
        int ks = idx >> 10;
        int gg = lane >> 2, tg = lane & 3;
        int k = ks * 8 + tg + 4 * r;
        int n = nt * 8 + gg;
        g_Wfrag[idx] = f2tf(Wsh[k * F + n]);
    }
}

// ---------------- tf32 tensor-core GEMM + fused alpha ----------------
// C[M,128] = A[M,128] @ W' + b', optional relu; optional alpha epilogue
#define GEMM_SMEM ((128 * 132 + F * F + 3 * F) * 4)

__global__ __launch_bounds__(256, 1) void k_gemm(const float* __restrict__ ext_in, int sel_in,
                                                 int sel_out, int M, int relu, int do_alpha,
                                                 const float* __restrict__ asrc,
                                                 const float* __restrict__ adst) {
    extern __shared__ float sm[];
    float* As = sm;                                  // 128*132 (tf32 bits)
    unsigned* Bf = (unsigned*)(sm + 128 * 132);      // 16384
    float* bsh = (float*)(Bf + F * F);               // 128
    float* sas = bsh + F;
    float* sad = sas + F;
    const float* A = sel_ptr(sel_in, ext_in);
    float* C = sel_ptr_w(sel_out);
    int tid = threadIdx.x;
    int row0 = blockIdx.x * 128;

    for (int t = tid; t < 128 * 32; t += 256) {
        int r = t >> 5, c4 = t & 31;
        int gr = row0 + r;
        float4 v = make_float4(0.f, 0.f, 0.f, 0.f);
        if (gr < M) v = *(const float4*)(A + (size_t)gr * F + c4 * 4);
        int base = r * 132 + c4 * 4;
        As[base + 0] = __uint_as_float(f2tf(v.x));
        As[base + 1] = __uint_as_float(f2tf(v.y));
        As[base + 2] = __uint_as_float(f2tf(v.z));
        As[base + 3] = __uint_as_float(f2tf(v.w));
    }
    for (int t = tid; t < F * F / 4; t += 256)
        ((uint4*)Bf)[t] = ((const uint4*)g_Wfrag)[t];
    if (tid < 128) {
        bsh[tid] = g_bf[tid];
        if (do_alpha) {
            sas[tid] = asrc[tid];
            sad[tid] = adst[tid];
        }
    }
    __syncthreads();

    int wid = tid >> 5, lane = tid & 31;
    int wm = wid >> 1, wn = wid & 1;
    int g = lane >> 2, tig = lane & 3;
    float acc[2][8][4];
#pragma unroll
    for (int mt = 0; mt < 2; mt++)
#pragma unroll
        for (int tn = 0; tn < 8; tn++)
#pragma unroll
            for (int j = 0; j < 4; j++) acc[mt][tn][j] = 0.f;

    const uint2* Bf2 = (const uint2*)Bf;
#pragma unroll
    for (int ks = 0; ks < 16; ks++) {
        unsigned a[2][4];
#pragma unroll
        for (int mt = 0; mt < 2; mt++) {
            const float* p = As + (wm * 32 + mt * 16 + g) * 132 + ks * 8 + tig;
            a[mt][0] = __float_as_uint(p[0]);
            a[mt][1] = __float_as_uint(p[8 * 132]);
            a[mt][2] = __float_as_uint(p[4]);
            a[mt][3] = __float_as_uint(p[8 * 132 + 4]);
        }
#pragma unroll
        for (int tn = 0; tn < 8; tn++) {
            int nt = wn * 8 + tn;
            uint2 b = Bf2[(ks * 16 + nt) * 32 + lane];
            mma_tf32(acc[0][tn], a[0], b.x, b.y);
            mma_tf32(acc[1][tn], a[1], b.x, b.y);
        }
    }

    float ps[2][2][2], pd[2][2][2];
#pragma unroll
    for (int mt = 0; mt < 2; mt++)
#pragma unroll
        for (int m01 = 0; m01 < 2; m01++)
#pragma unroll
            for (int hl = 0; hl < 2; hl++) {
                ps[mt][m01][hl] = 0.f;
                pd[mt][m01][hl] = 0.f;
            }

#pragma unroll
    for (int mt = 0; mt < 2; mt++) {
        int rA = row0 + wm * 32 + mt * 16 + g;
#pragma unroll
        for (int tn = 0; tn < 8; tn++) {
            int c0 = wn * 64 + tn * 8 + 2 * tig;
            float b0 = bsh[c0], b1 = bsh[c0 + 1];
            float v0 = acc[mt][tn][0] + b0;
            float v1 = acc[mt][tn][1] + b1;
            float v2 = acc[mt][tn][2] + b0;
            float v3 = acc[mt][tn][3] + b1;
            if (relu) {
                v0 = fmaxf(v0, 0.f); v1 = fmaxf(v1, 0.f);
                v2 = fmaxf(v2, 0.f); v3 = fmaxf(v3, 0.f);
            }
            if (rA < M) *(float2*)(C + (size_t)rA * F + c0) = make_float2(v0, v1);
            if (rA + 8 < M) *(float2*)(C + (size_t)(rA + 8) * F + c0) = make_float2(v2, v3);
            if (do_alpha) {
                int hl = tn >> 2;
                float s0 = sas[c0], s1 = sas[c0 + 1];
                float d0 = sad[c0], d1 = sad[c0 + 1];
                ps[mt][0][hl] += v0 * s0 + v1 * s1;
                pd[mt][0][hl] += v0 * d0 + v1 * d1;
                ps[mt][1][hl] += v2 * s0 + v3 * s1;
                pd[mt][1][hl] += v2 * d0 + v3 * d1;
            }
        }
    }

    if (do_alpha) {
#pragma unroll
        for (int mt = 0; mt < 2; mt++)
#pragma unroll
            for (int m01 = 0; m01 < 2; m01++)
#pragma unroll
                for (int hl = 0; hl < 2; hl++) {
                    float v = ps[mt][m01][hl];
                    v += __shfl_xor_sync(0xffffffffu, v, 1);
                    v += __shfl_xor_sync(0xffffffffu, v, 2);
                    ps[mt][m01][hl] = v;
                    float w = pd[mt][m01][hl];
                    w += __shfl_xor_sync(0xffffffffu, w, 1);
                    w += __shfl_xor_sync(0xffffffffu, w, 2);
                    pd[mt][m01][hl] = w;
                }
        if (tig == 0) {
#pragma unroll
            for (int mt = 0; mt < 2; mt++)
#pragma unroll
                for (int m01 = 0; m01 < 2; m01++) {
                    int row = row0 + wm * 32 + mt * 16 + m01 * 8 + g;
                    if (row < M) {
#pragma unroll
                        for (int hl = 0; hl < 2; hl++) {
                            int head = wn * 2 + hl;
                            g_als[row * 4 + head] = ps[mt][m01][hl];
                            g_ald[row * 4 + head] = pd[mt][m01][hl];
                        }
                    }
                }
        }
    }
}

// ---------------- aggregation: warp per dst node (max-free softmax) ----------------
__global__ __launch_bounds__(256) void k_agg(const float* __restrict__ gbias, int sel_out) {
    float* out = sel_ptr_w(sel_out);
    int gw = (blockIdx.x * blockDim.x + threadIdx.x) >> 5;
    int lane = threadIdx.x & 31;
    if (gw >= NN) return;
    int s0 = g_off[gw], s1 = g_off[gw + 1];
    int h = lane >> 3;
    float aldh = g_ald[gw * 4 + h];

    float a0 = 0.f, a1 = 0.f, a2 = 0.f, a3 = 0.f, ss = 0.f;
    const float4* hp4 = (const float4*)g_hp;
    for (int e = s0; e < s1; ++e) {
        int s = g_csrc[e];
        float l = g_als[s * 4 + h] + aldh;
        l = l > 0.f ? l : 0.2f * l;
        float wgt = __expf(l);
        ss += wgt;
        float4 v = hp4[(size_t)s * 32 + lane];
        a0 += wgt * v.x;
        a1 += wgt * v.y;
        a2 += wgt * v.z;
        a3 += wgt * v.w;
    }
    float inv = 1.0f / (ss + 1e-16f);
    float4 gb = ((const float4*)gbias)[lane];
    float4 o;
    o.x = fmaxf(a0 * inv + gb.x, 0.f);
    o.y = fmaxf(a1 * inv + gb.y, 0.f);
    o.z = fmaxf(a2 * inv + gb.z, 0.f);
    o.w = fmaxf(a3 * inv + gb.w, 0.f);
    ((float4*)out)[(size_t)gw * 32 + lane] = o;
}

// ---------------- pooling (batch sorted) ----------------
__global__ void k_pool(const int* __restrict__ batch, int sel_in) {
    const float* X = sel_ptr(sel_in, nullptr);
    __shared__ int bsh[64];
    int r0 = blockIdx.x * 64;
    int tid = threadIdx.x;  // 128
    int nr = NN - r0;
    if (nr > 64) nr = 64;
    if (tid < nr) bsh[tid] = batch[r0 + tid];
    __syncthreads();
    float acc = 0.f;
    int cur = bsh[0];
    for (int j = 0; j < nr; j++) {
        int b = bsh[j];
        if (b != cur) {
            atomicAdd(&g_pool[(size_t)cur * F + tid], acc);
            acc = 0.f;
            cur = b;
        }
        acc += X[(size_t)(r0 + j) * F + tid];
    }
    atomicAdd(&g_pool[(size_t)cur * F + tid], acc);
}

// ---------------- final head: BN + cls GEMM + log_softmax ----------------
__global__ void k_head(const float* __restrict__ bnh_g, const float* __restrict__ bnh_b,
                       const float* __restrict__ cls_w, const float* __restrict__ cls_b,
                       float* __restrict__ out) {
    __shared__ float sc[F], shf[F];
    int r = blockIdx.x;       // 256 rows
    int lane = threadIdx.x;   // 32 threads
    const float invM = 1.0f / (float)NG;
    for (int c = lane; c < F; c += 32) {
        float mean = g_stats[c] * invM;
        float var = g_stats[F + c] * invM - mean * mean;
        float rs = rsqrtf(var + 1e-5f);
        float s = rs * bnh_g[c];
        sc[c] = s;
        shf[c] = bnh_b[c] - mean * s;
    }
    __syncwarp();
    float logit = 0.f;
    if (lane < NCLS) {
        logit = cls_b[lane];
        for (int c = 0; c < F; c++)
            logit += (g_gbuf[(size_t)r * F + c] * sc[c] + shf[c]) * cls_w[c * NCLS + lane];
    }
    float v = (lane < NCLS) ? logit : -3.0e38f;
    float m = v;
#pragma unroll
    for (int o = 16; o; o >>= 1) m = fmaxf(m, __shfl_xor_sync(0xffffffffu, m, o));
    float e = (lane < NCLS) ? __expf(v - m) : 0.f;
    float s = e;
#pragma unroll
    for (int o = 16; o; o >>= 1) s += __shfl_xor_sync(0xffffffffu, s, o);
    if (lane < NCLS) out[r * NCLS + lane] = v - m - logf(s);
}

// ---------------- host ----------------
extern "C" void kernel_launch(void* const* d_in, const int* in_sizes, int n_in,
                              void* d_out, int out_size) {
    const float* x       = (const float*)d_in[0];
    const int*   ei      = (const int*)d_in[1];
    const int*   batch   = (const int*)d_in[2];
    const float* w_feat  = (const float*)d_in[3];
    const float* bnf_g   = (const float*)d_in[4];
    const float* bnf_b   = (const float*)d_in[5];
    const float* bnc_g   = (const float*)d_in[6];
    const float* bnc_b   = (const float*)d_in[7];
    const float* gat_w   = (const float*)d_in[8];
    const float* gat_as  = (const float*)d_in[9];
    const float* gat_ad  = (const float*)d_in[10];
    const float* gat_b   = (const float*)d_in[11];
    const float* bnfc_g  = (const float*)d_in[12];
    const float* bnfc_b  = (const float*)d_in[13];
    const float* lin_w   = (const float*)d_in[14];
    const float* lin_b   = (const float*)d_in[15];
    const float* bnh_g   = (const float*)d_in[16];
    const float* bnh_b   = (const float*)d_in[17];
    const float* cls_w   = (const float*)d_in[18];
    const float* cls_b   = (const float*)d_in[19];
    float* out = (float*)d_out;

    cudaFuncSetAttribute(k_gemm, cudaFuncAttributeMaxDynamicSharedMemorySize, GEMM_SMEM);
    cudaFuncSetAttribute(k_fold, cudaFuncAttributeMaxDynamicSharedMemorySize, F * F * 4);

    // init + CSR + feature layer (interleaved so ncu -s 5 lands on k_gemm)
    k_zeroall<<<(NN + 255) / 256, 256>>>();
    k_count<<<(NE + 255) / 256, 256>>>(ei);
    k_colstats<<<(NN + 63) / 64, 128>>>(x, 0, NN);
    k_fold<<<1, 128, F * F * 4>>>(w_feat, bnf_g, bnf_b, nullptr, 1.0f / (float)NN);
    k_scanA<<<SCAN_NB, SCAN_B>>>();
    k_gemm<<<(NN + 127) / 128, 256, GEMM_SMEM>>>(x, 0, 1, NN, 1, 0, nullptr, nullptr);
    k_scanB<<<1, 128>>>();
    k_scanC<<<(NN + 255) / 256, 256>>>();
    k_fill<<<(NE + NN + 255) / 256, 256>>>(ei);

    // ---- 3 GAT convs ----
    int sel_in = 1, sel_out = 2;
    for (int i = 0; i < 3; i++) {
        k_colstats<<<(NN + 63) / 64, 128>>>(nullptr, sel_in, NN);
        k_fold<<<1, 128, F * F * 4>>>(gat_w + (size_t)i * F * F, bnc_g + i * F, bnc_b + i * F,
                                      nullptr, 1.0f / (float)NN);
        k_gemm<<<(NN + 127) / 128, 256, GEMM_SMEM>>>(nullptr, sel_in, 3, NN, 0, 1,
                                                     gat_as + i * F, gat_ad + i * F);
        k_agg<<<(NN + 7) / 8, 256>>>(gat_b + i * F, sel_out);
        int t = sel_in; sel_in = sel_out; sel_out = t;
    }
    // final conv output now in sel_in (g_h1)

    // ---- pooling ----
    k_pool<<<(NN + 63) / 64, 128>>>(batch, sel_in);

    // ---- lin layer: gbuf = relu(BN(pool) @ lin_w + lin_b) ----
    k_colstats<<<(NG + 63) / 64, 128>>>(nullptr, 4, NG);
    k_fold<<<1, 128, F * F * 4>>>(lin_w, bnfc_g, bnfc_b, lin_b, 1.0f / (float)NG);
    k_gemm<<<(NG + 127) / 128, 256, GEMM_SMEM>>>(nullptr, 4, 5, NG, 1, 0, nullptr, nullptr);

    // ---- head: BN(gbuf) @ cls + log_softmax ----
    k_colstats<<<(NG + 63) / 64, 128>>>(nullptr, 5, NG);
    k_head<<<NG, 32>>>(bnh_g, bnh_b, cls_w, cls_b, out);
}